// round 4
// baseline (speedup 1.0000x reference)
#include <cuda_runtime.h>

#define NN 50000
#define EE 800000
#define NEG 0.2f

typedef unsigned long long u64;

// ---------------- scratch (static device globals; no allocation) ----------------
__device__ __align__(16) float    g_gl1[NN * 128];
__device__ __align__(16) float    g_gr1[NN * 128];
__device__ __align__(16) float    g_h1 [NN * 128];
__device__ __align__(16) float    g_gl2[NN * 32];
__device__ __align__(16) float    g_gr2[NN * 32];
// CSR by dst
__device__ unsigned g_cnt[NN];
__device__ unsigned g_rowstart[NN];
__device__ unsigned g_cursor[NN];
__device__ int      g_csrc[EE];

// ---------------- f32x2 helpers ----------------
__device__ __forceinline__ u64 pack2(float lo, float hi) {
    u64 r;
    asm("mov.b64 %0, {%1, %2};" : "=l"(r) : "f"(lo), "f"(hi));
    return r;
}
__device__ __forceinline__ float2 unpack2(u64 v) {
    float2 r;
    asm("mov.b64 {%0, %1}, %2;" : "=f"(r.x), "=f"(r.y) : "l"(v));
    return r;
}
__device__ __forceinline__ void ffma2(u64& d, u64 a, u64 b) {
    asm("fma.rn.f32x2 %0, %1, %2, %0;" : "+l"(d) : "l"(a), "l"(b));
}

// ---------------- CSR build ----------------
__global__ void csr_init_kernel() {
    int i = blockIdx.x * blockDim.x + threadIdx.x;
    if (i < NN) g_cnt[i] = 0u;
}
__global__ void csr_hist_kernel(const int* __restrict__ ei) {
    int i = blockIdx.x * blockDim.x + threadIdx.x;
    if (i < EE) atomicAdd(&g_cnt[ei[EE + i]], 1u);
}
__global__ __launch_bounds__(1024) void csr_scan_kernel() {
    __shared__ unsigned s[1024];
    const int T = 1024;
    const int CH = (NN + T - 1) / T;
    int t = threadIdx.x;
    int base = t * CH;
    unsigned sum = 0;
    for (int i = 0; i < CH; i++) {
        int j = base + i;
        if (j < NN) sum += g_cnt[j];
    }
    s[t] = sum;
    __syncthreads();
    for (int off = 1; off < T; off <<= 1) {
        unsigned u = (t >= off) ? s[t - off] : 0u;
        __syncthreads();
        s[t] += u;
        __syncthreads();
    }
    unsigned run = s[t] - sum;
    for (int i = 0; i < CH; i++) {
        int j = base + i;
        if (j < NN) {
            unsigned c = g_cnt[j];
            g_rowstart[j] = run;
            g_cursor[j]   = run;
            run += c;
        }
    }
}
__global__ void csr_fill_kernel(const int* __restrict__ ei) {
    int i = blockIdx.x * blockDim.x + threadIdx.x;
    if (i < EE) {
        int d = ei[EE + i];
        unsigned pos = atomicAdd(&g_cursor[d], 1u);
        g_csrc[pos] = ei[i];
    }
}

// ---------------- GEMM (one weight matrix per block; grid.y picks W1/W2) ---------
// A:[n,128], W:[128,M]. 64 rows/block, 256 threads (16x16), thread tile 4 x (M/16).
template <int M>
__global__ __launch_bounds__(256) void gemm_one_kernel(
    const float* __restrict__ A, int n,
    const float* __restrict__ W1, const float* __restrict__ b1, float* __restrict__ C1,
    const float* __restrict__ W2, const float* __restrict__ b2, float* __restrict__ C2)
{
    constexpr int K  = 128;
    constexpr int RB = 64;
    constexpr int TN = M / 16;       // 8 (M=128) or 2 (M=32)
    constexpr int TP = TN / 2;       // pairs: 4 or 1
    extern __shared__ float sm[];
    float* As = sm;                  // RB*K = 8192 floats (32 KB)
    float* Ws = As + RB * K;         // K*M

    const float* __restrict__ W = blockIdx.y ? W2 : W1;
    const float* __restrict__ b = blockIdx.y ? b2 : b1;
    float* __restrict__       C = blockIdx.y ? C2 : C1;

    const int tid  = threadIdx.x;
    const int row0 = blockIdx.x * RB;

    for (int i = tid; i < RB * K / 4; i += 256) {
        int r  = i >> 5;             // K/4 = 32
        int c4 = i & 31;
        int gr_ = row0 + r;
        float4 v = make_float4(0.f, 0.f, 0.f, 0.f);
        if (gr_ < n) v = reinterpret_cast<const float4*>(A)[gr_ * 32 + c4];
        reinterpret_cast<float4*>(As)[i] = v;
    }
    for (int i = tid; i < K * M / 4; i += 256) {
        reinterpret_cast<float4*>(Ws)[i] = reinterpret_cast<const float4*>(W)[i];
    }
    __syncthreads();

    const int tx = tid & 15;
    const int ty = tid >> 4;

    u64 acc[4][TP];
    const u64 zz = pack2(0.f, 0.f);
#pragma unroll
    for (int i = 0; i < 4; i++)
#pragma unroll
        for (int j = 0; j < TP; j++) acc[i][j] = zz;

    for (int k = 0; k < K; ++k) {
        u64 ap[4];
#pragma unroll
        for (int i = 0; i < 4; i++) {
            float a = As[(ty * 4 + i) * K + k];
            ap[i] = pack2(a, a);
        }
        u64 wp[TP];
        const u64* pw = reinterpret_cast<const u64*>(Ws + k * M + tx * TN);
#pragma unroll
        for (int j = 0; j < TP; j++) wp[j] = pw[j];
#pragma unroll
        for (int i = 0; i < 4; i++)
#pragma unroll
            for (int j = 0; j < TP; j++) ffma2(acc[i][j], ap[i], wp[j]);
    }

#pragma unroll
    for (int i = 0; i < 4; i++) {
        int r = row0 + ty * 4 + i;
        if (r < n) {
#pragma unroll
            for (int j = 0; j < TP; j++) {
                int c = tx * TN + j * 2;
                float2 v = unpack2(acc[i][j]);
                C[r * M + c]     = v.x + b[c];
                C[r * M + c + 1] = v.y + b[c + 1];
            }
        }
    }
}

// ---------------- layer 1: fused attention aggregation (warp per dst) ----------------
// lane l holds float4 channels [4l,4l+3] (head l>>3); head reduce = 3 shfls.
// Depth-2 software pipeline on the 512B gathers.
__global__ __launch_bounds__(256) void agg1_kernel(const float* __restrict__ att,
                                                   const float* __restrict__ bias) {
    const int lane = threadIdx.x & 31;
    const int d = blockIdx.x * (blockDim.x >> 5) + (threadIdx.x >> 5);
    if (d >= NN) return;

    const float4* __restrict__ gl4 = reinterpret_cast<const float4*>(g_gl1);
    const float4  grd = reinterpret_cast<const float4*>(g_gr1)[d * 32 + lane];
    const float4  at  = reinterpret_cast<const float4*>(att)[lane];

    float4 acc = make_float4(0.f, 0.f, 0.f, 0.f);
    float  den = 0.f;

    const unsigned start = g_rowstart[d];
    const unsigned deg   = g_cnt[d];

    // item 0 = self loop (s=d), items 1..deg = CSR edges; clamp OOB src to d.
    int s1 = (deg > 0) ? g_csrc[start]     : d;
    int s2 = (deg > 1) ? g_csrc[start + 1] : d;
    float4 gcur  = gl4[d  * 32 + lane];
    float4 gnext = gl4[s1 * 32 + lane];

    for (unsigned j = 0; j <= deg; ++j) {
        float4 gnn = gl4[s2 * 32 + lane];               // prefetch j+2 (clamped safe)
        s2 = (j + 3 <= deg) ? g_csrc[start + j + 2] : d;

        float m0 = gcur.x + grd.x; m0 = (m0 > 0.f) ? m0 : NEG * m0;
        float m1 = gcur.y + grd.y; m1 = (m1 > 0.f) ? m1 : NEG * m1;
        float m2 = gcur.z + grd.z; m2 = (m2 > 0.f) ? m2 : NEG * m2;
        float m3 = gcur.w + grd.w; m3 = (m3 > 0.f) ? m3 : NEG * m3;
        float p = at.x * m0 + at.y * m1 + at.z * m2 + at.w * m3;
        p += __shfl_xor_sync(0xffffffffu, p, 1);
        p += __shfl_xor_sync(0xffffffffu, p, 2);
        p += __shfl_xor_sync(0xffffffffu, p, 4);
        float w = __expf(p);
        acc.x += w * gcur.x;
        acc.y += w * gcur.y;
        acc.z += w * gcur.z;
        acc.w += w * gcur.w;
        den += w;

        gcur = gnext;
        gnext = gnn;
    }

    const float inv = 1.f / den;
    const float4 b = reinterpret_cast<const float4*>(bias)[lane];
    float v0 = acc.x * inv + b.x; v0 = (v0 > 0.f) ? v0 : expm1f(v0);
    float v1 = acc.y * inv + b.y; v1 = (v1 > 0.f) ? v1 : expm1f(v1);
    float v2 = acc.z * inv + b.z; v2 = (v2 > 0.f) ? v2 : expm1f(v2);
    float v3 = acc.w * inv + b.w; v3 = (v3 > 0.f) ? v3 : expm1f(v3);
    reinterpret_cast<float4*>(g_h1)[d * 32 + lane] = make_float4(v0, v1, v2, v3);
}

// ---------------- layer 2: aggregation, 4 dsts per warp (8 lanes / dst) -------------
// Lane = grp*8 + lg; grp handles dst d, lane holds channels [4lg, 4lg+3] as float4.
// 3 shfl_xor(1,2,4) reduce within each 8-lane group -> 4 edges per shfl triple.
__global__ __launch_bounds__(256) void agg2_kernel(const float* __restrict__ att,
                                                   const float* __restrict__ bias,
                                                   float* __restrict__ out) {
    const int lane = threadIdx.x & 31;
    const int grp  = lane >> 3;
    const int lg   = lane & 7;
    const int wid  = blockIdx.x * (blockDim.x >> 5) + (threadIdx.x >> 5);
    int d = wid * 4 + grp;
    const bool dvalid = (d < NN);
    if (d >= NN) d = NN - 1;   // clamp; results discarded

    const float4* __restrict__ gl4 = reinterpret_cast<const float4*>(g_gl2);
    const float4 grd  = reinterpret_cast<const float4*>(g_gr2)[d * 8 + lg];
    const float4 at   = reinterpret_cast<const float4*>(att)[lg];

    const unsigned start = g_rowstart[d];
    const unsigned deg   = dvalid ? g_cnt[d] : 0u;

    // warp-wide max degree (all lanes participate)
    unsigned mdeg = deg;
#pragma unroll
    for (int off = 8; off < 32; off <<= 1) {
        unsigned o = __shfl_xor_sync(0xffffffffu, mdeg, off);
        mdeg = (o > mdeg) ? o : mdeg;
    }

    float4 acc = make_float4(0.f, 0.f, 0.f, 0.f);
    float  den = 0.f;

    int snext = (deg > 0) ? g_csrc[start] : d;     // src of item 1
    float4 g = gl4[d * 8 + lg];                    // item 0 = self loop

    for (unsigned j = 0; j <= mdeg; ++j) {
        float4 gc = g;
        // prefetch next item (clamped to d when beyond this group's degree)
        int snn = (j + 2 <= deg) ? g_csrc[start + j + 1] : d;
        g = gl4[snext * 8 + lg];
        snext = snn;

        float m0 = gc.x + grd.x; m0 = (m0 > 0.f) ? m0 : NEG * m0;
        float m1 = gc.y + grd.y; m1 = (m1 > 0.f) ? m1 : NEG * m1;
        float m2 = gc.z + grd.z; m2 = (m2 > 0.f) ? m2 : NEG * m2;
        float m3 = gc.w + grd.w; m3 = (m3 > 0.f) ? m3 : NEG * m3;
        float p = at.x * m0 + at.y * m1 + at.z * m2 + at.w * m3;
        p += __shfl_xor_sync(0xffffffffu, p, 1);
        p += __shfl_xor_sync(0xffffffffu, p, 2);
        p += __shfl_xor_sync(0xffffffffu, p, 4);
        float w = (j <= deg) ? __expf(p) : 0.f;
        acc.x += w * gc.x;
        acc.y += w * gc.y;
        acc.z += w * gc.z;
        acc.w += w * gc.w;
        den += w;
    }

    if (dvalid) {
        const float inv = 1.f / den;
        const float4 b = reinterpret_cast<const float4*>(bias)[lg];
        reinterpret_cast<float4*>(out)[d * 8 + lg] =
            make_float4(acc.x * inv + b.x, acc.y * inv + b.y,
                        acc.z * inv + b.z, acc.w * inv + b.w);
    }
}

// ---------------- launch ----------------
extern "C" void kernel_launch(void* const* d_in, const int* in_sizes, int n_in,
                              void* d_out, int out_size) {
    const float* x    = (const float*)d_in[0];
    const int*   ei   = (const int*)d_in[1];
    const float* Wl1  = (const float*)d_in[2];
    const float* bl1  = (const float*)d_in[3];
    const float* Wr1  = (const float*)d_in[4];
    const float* br1  = (const float*)d_in[5];
    const float* att1 = (const float*)d_in[6];
    const float* bias1= (const float*)d_in[7];
    const float* Wl2  = (const float*)d_in[8];
    const float* bl2  = (const float*)d_in[9];
    const float* Wr2  = (const float*)d_in[10];
    const float* br2  = (const float*)d_in[11];
    const float* att2 = (const float*)d_in[12];
    const float* bias2= (const float*)d_in[13];
    float* out = (float*)d_out;

    cudaFuncSetAttribute(gemm_one_kernel<128>,
                         cudaFuncAttributeMaxDynamicSharedMemorySize, 98304);
    cudaFuncSetAttribute(gemm_one_kernel<32>,
                         cudaFuncAttributeMaxDynamicSharedMemorySize, 49152);

    float *gl1p, *gr1p, *h1p, *gl2p, *gr2p;
    cudaGetSymbolAddress((void**)&gl1p, g_gl1);
    cudaGetSymbolAddress((void**)&gr1p, g_gr1);
    cudaGetSymbolAddress((void**)&h1p,  g_h1);
    cudaGetSymbolAddress((void**)&gl2p, g_gl2);
    cudaGetSymbolAddress((void**)&gr2p, g_gr2);

    const int gemmRows = (NN + 63) / 64;

    // slots 1-3: CSR prefix; slot 4: gemm1 (gets profiled by ncu -s 5 -c 1)
    csr_init_kernel<<<(NN + 255) / 256, 256>>>();
    csr_hist_kernel<<<(EE + 255) / 256, 256>>>(ei);
    csr_scan_kernel<<<1, 1024>>>();
    gemm_one_kernel<128><<<dim3(gemmRows, 2), 256, 98304>>>(
        x, NN, Wl1, bl1, gl1p, Wr1, br1, gr1p);
    csr_fill_kernel<<<(EE + 255) / 256, 256>>>(ei);

    agg1_kernel<<<(NN + 7) / 8, 256>>>(att1, bias1);

    gemm_one_kernel<32><<<dim3(gemmRows, 2), 256, 49152>>>(
        h1p, NN, Wl2, bl2, gl2p, Wr2, br2, gr2p);
    agg2_kernel<<<(NN + 31) / 32, 256>>>(att2, bias2, out);
}

// round 5
// speedup vs baseline: 1.1090x; 1.1090x over previous
#include <cuda_runtime.h>

#define NN 50000
#define EE 800000
#define NEG 0.2f

typedef unsigned long long u64;

// ---------------- scratch (static device globals; no allocation) ----------------
__device__ __align__(16) float    g_gl1[NN * 128];
__device__ __align__(16) float    g_gr1[NN * 128];
__device__ __align__(16) float    g_h1 [NN * 128];
__device__ __align__(16) float    g_gl2[NN * 32];
__device__ __align__(16) float    g_gr2[NN * 32];
// CSR by dst
__device__ unsigned g_cnt[NN];
__device__ unsigned g_rowstart[NN];
__device__ unsigned g_cursor[NN];
__device__ int      g_csrc[EE];

// ---------------- f32x2 helpers ----------------
__device__ __forceinline__ u64 pack2(float lo, float hi) {
    u64 r;
    asm("mov.b64 %0, {%1, %2};" : "=l"(r) : "f"(lo), "f"(hi));
    return r;
}
__device__ __forceinline__ float2 unpack2(u64 v) {
    float2 r;
    asm("mov.b64 {%0, %1}, %2;" : "=f"(r.x), "=f"(r.y) : "l"(v));
    return r;
}
__device__ __forceinline__ void ffma2(u64& d, u64 a, u64 b) {
    asm("fma.rn.f32x2 %0, %1, %2, %0;" : "+l"(d) : "l"(a), "l"(b));
}

// ---------------- CSR build ----------------
__global__ void csr_init_kernel() {
    int i = blockIdx.x * blockDim.x + threadIdx.x;
    if (i < NN) g_cnt[i] = 0u;
}
__global__ void csr_hist_kernel(const int* __restrict__ ei) {
    int i = blockIdx.x * blockDim.x + threadIdx.x;
    if (i < EE) atomicAdd(&g_cnt[ei[EE + i]], 1u);
}
__global__ __launch_bounds__(1024) void csr_scan_kernel() {
    __shared__ unsigned s[1024];
    const int T = 1024;
    const int CH = (NN + T - 1) / T;
    int t = threadIdx.x;
    int base = t * CH;
    unsigned sum = 0;
    for (int i = 0; i < CH; i++) {
        int j = base + i;
        if (j < NN) sum += g_cnt[j];
    }
    s[t] = sum;
    __syncthreads();
    for (int off = 1; off < T; off <<= 1) {
        unsigned u = (t >= off) ? s[t - off] : 0u;
        __syncthreads();
        s[t] += u;
        __syncthreads();
    }
    unsigned run = s[t] - sum;
    for (int i = 0; i < CH; i++) {
        int j = base + i;
        if (j < NN) {
            unsigned c = g_cnt[j];
            g_rowstart[j] = run;
            g_cursor[j]   = run;
            run += c;
        }
    }
}
__global__ void csr_fill_kernel(const int* __restrict__ ei) {
    int i = blockIdx.x * blockDim.x + threadIdx.x;
    if (i < EE) {
        int d = ei[EE + i];
        unsigned pos = atomicAdd(&g_cursor[d], 1u);
        g_csrc[pos] = ei[i];
    }
}

// ---------------- GEMM: LDS.128-only, 8x8 (or 8x4) register tile, f32x2 ----------
// A:[n,128] row-major; W:[128,M]; one weight matrix per block (blockIdx.y).
// 128 threads. Thread grid TXN x TYN; thread tile RT rows x CT cols.
template <int M, int CT, int RB>
__global__ __launch_bounds__(128) void gemm_kernel(
    const float* __restrict__ A, int n,
    const float* __restrict__ W1, const float* __restrict__ b1, float* __restrict__ C1,
    const float* __restrict__ W2, const float* __restrict__ b2, float* __restrict__ C2)
{
    constexpr int K   = 128;
    constexpr int TXN = M / CT;       // threads along N
    constexpr int TYN = 128 / TXN;    // threads along rows
    constexpr int RT  = RB / TYN;     // rows per thread (8)
    constexpr int CP  = CT / 2;       // f32x2 pairs per thread

    extern __shared__ float sm[];
    float* As = sm;                   // RB x K (row-major)
    float* Ws = As + RB * K;          // K x M  (row-major)

    const float* __restrict__ W = blockIdx.y ? W2 : W1;
    const float* __restrict__ b = blockIdx.y ? b2 : b1;
    float* __restrict__       C = blockIdx.y ? C2 : C1;

    const int tid  = threadIdx.x;
    const int row0 = blockIdx.x * RB;

    // fill A tile (coalesced float4; K/4 = 32 per row)
    for (int i = tid; i < RB * 32; i += 128) {
        int r  = i >> 5;
        int c4 = i & 31;
        int gr_ = row0 + r;
        float4 v = make_float4(0.f, 0.f, 0.f, 0.f);
        if (gr_ < n) v = reinterpret_cast<const float4*>(A)[gr_ * 32 + c4];
        reinterpret_cast<float4*>(As)[i] = v;
    }
    // fill W tile
    for (int i = tid; i < K * M / 4; i += 128) {
        reinterpret_cast<float4*>(Ws)[i] = reinterpret_cast<const float4*>(W)[i];
    }
    __syncthreads();

    const int tx = tid % TXN;
    const int ty = tid / TXN;

    u64 acc[RT][CP];
    const u64 zz = pack2(0.f, 0.f);
#pragma unroll
    for (int i = 0; i < RT; i++)
#pragma unroll
        for (int j = 0; j < CP; j++) acc[i][j] = zz;

    const float4* As4 = reinterpret_cast<const float4*>(As);

    for (int k4 = 0; k4 < K / 4; ++k4) {
        // A: one float4 (4 k-values) per row — LDS.128, warp-broadcast
        float aa[4][RT];
#pragma unroll
        for (int i = 0; i < RT; i++) {
            float4 v = As4[(ty * RT + i) * 32 + k4];
            aa[0][i] = v.x; aa[1][i] = v.y; aa[2][i] = v.z; aa[3][i] = v.w;
        }
#pragma unroll
        for (int kk = 0; kk < 4; ++kk) {
            // W row slice: CP u64 = CP/2 LDS.128 (16B-aligned, contiguous per warp)
            u64 wv[CP];
            const float* wrow = Ws + (k4 * 4 + kk) * M + tx * CT;
#pragma unroll
            for (int j2 = 0; j2 < CP / 2; ++j2) {
                ulonglong2 u = reinterpret_cast<const ulonglong2*>(wrow)[j2];
                wv[j2 * 2]     = u.x;
                wv[j2 * 2 + 1] = u.y;
            }
            if constexpr (CP % 2) {
                wv[CP - 1] = reinterpret_cast<const u64*>(wrow)[CP - 1];
            }
#pragma unroll
            for (int i = 0; i < RT; i++) {
                u64 ap = pack2(aa[kk][i], aa[kk][i]);
#pragma unroll
                for (int j = 0; j < CP; j++) ffma2(acc[i][j], ap, wv[j]);
            }
        }
    }

#pragma unroll
    for (int i = 0; i < RT; i++) {
        int r = row0 + ty * RT + i;
        if (r < n) {
#pragma unroll
            for (int j = 0; j < CP; j++) {
                int c = tx * CT + j * 2;
                float2 v = unpack2(acc[i][j]);
                C[r * M + c]     = v.x + b[c];
                C[r * M + c + 1] = v.y + b[c + 1];
            }
        }
    }
}

// ---------------- layer 1: fused attention aggregation (warp per dst) ----------------
__global__ __launch_bounds__(256) void agg1_kernel(const float* __restrict__ att,
                                                   const float* __restrict__ bias) {
    const int lane = threadIdx.x & 31;
    const int d = blockIdx.x * (blockDim.x >> 5) + (threadIdx.x >> 5);
    if (d >= NN) return;

    const float4* __restrict__ gl4 = reinterpret_cast<const float4*>(g_gl1);
    const float4  grd = reinterpret_cast<const float4*>(g_gr1)[d * 32 + lane];
    const float4  at  = reinterpret_cast<const float4*>(att)[lane];

    float4 acc = make_float4(0.f, 0.f, 0.f, 0.f);
    float  den = 0.f;

    const unsigned start = g_rowstart[d];
    const unsigned deg   = g_cnt[d];

    int s1 = (deg > 0) ? g_csrc[start]     : d;
    int s2 = (deg > 1) ? g_csrc[start + 1] : d;
    float4 gcur  = gl4[d  * 32 + lane];
    float4 gnext = gl4[s1 * 32 + lane];

    for (unsigned j = 0; j <= deg; ++j) {
        float4 gnn = gl4[s2 * 32 + lane];
        s2 = (j + 3 <= deg) ? g_csrc[start + j + 2] : d;

        float m0 = gcur.x + grd.x; m0 = (m0 > 0.f) ? m0 : NEG * m0;
        float m1 = gcur.y + grd.y; m1 = (m1 > 0.f) ? m1 : NEG * m1;
        float m2 = gcur.z + grd.z; m2 = (m2 > 0.f) ? m2 : NEG * m2;
        float m3 = gcur.w + grd.w; m3 = (m3 > 0.f) ? m3 : NEG * m3;
        float p = at.x * m0 + at.y * m1 + at.z * m2 + at.w * m3;
        p += __shfl_xor_sync(0xffffffffu, p, 1);
        p += __shfl_xor_sync(0xffffffffu, p, 2);
        p += __shfl_xor_sync(0xffffffffu, p, 4);
        float w = __expf(p);
        acc.x += w * gcur.x;
        acc.y += w * gcur.y;
        acc.z += w * gcur.z;
        acc.w += w * gcur.w;
        den += w;

        gcur = gnext;
        gnext = gnn;
    }

    const float inv = 1.f / den;
    const float4 b = reinterpret_cast<const float4*>(bias)[lane];
    float v0 = acc.x * inv + b.x; v0 = (v0 > 0.f) ? v0 : expm1f(v0);
    float v1 = acc.y * inv + b.y; v1 = (v1 > 0.f) ? v1 : expm1f(v1);
    float v2 = acc.z * inv + b.z; v2 = (v2 > 0.f) ? v2 : expm1f(v2);
    float v3 = acc.w * inv + b.w; v3 = (v3 > 0.f) ? v3 : expm1f(v3);
    reinterpret_cast<float4*>(g_h1)[d * 32 + lane] = make_float4(v0, v1, v2, v3);
}

// ---------------- layer 2: aggregation, 4 dsts per warp (8 lanes / dst) -------------
__global__ __launch_bounds__(256) void agg2_kernel(const float* __restrict__ att,
                                                   const float* __restrict__ bias,
                                                   float* __restrict__ out) {
    const int lane = threadIdx.x & 31;
    const int grp  = lane >> 3;
    const int lg   = lane & 7;
    const int wid  = blockIdx.x * (blockDim.x >> 5) + (threadIdx.x >> 5);
    int d = wid * 4 + grp;
    const bool dvalid = (d < NN);
    if (d >= NN) d = NN - 1;

    const float4* __restrict__ gl4 = reinterpret_cast<const float4*>(g_gl2);
    const float4 grd  = reinterpret_cast<const float4*>(g_gr2)[d * 8 + lg];
    const float4 at   = reinterpret_cast<const float4*>(att)[lg];

    const unsigned start = g_rowstart[d];
    const unsigned deg   = dvalid ? g_cnt[d] : 0u;

    unsigned mdeg = deg;
#pragma unroll
    for (int off = 8; off < 32; off <<= 1) {
        unsigned o = __shfl_xor_sync(0xffffffffu, mdeg, off);
        mdeg = (o > mdeg) ? o : mdeg;
    }

    float4 acc = make_float4(0.f, 0.f, 0.f, 0.f);
    float  den = 0.f;

    int snext = (deg > 0) ? g_csrc[start] : d;
    float4 g = gl4[d * 8 + lg];

    for (unsigned j = 0; j <= mdeg; ++j) {
        float4 gc = g;
        int snn = (j + 2 <= deg) ? g_csrc[start + j + 1] : d;
        g = gl4[snext * 8 + lg];
        snext = snn;

        float m0 = gc.x + grd.x; m0 = (m0 > 0.f) ? m0 : NEG * m0;
        float m1 = gc.y + grd.y; m1 = (m1 > 0.f) ? m1 : NEG * m1;
        float m2 = gc.z + grd.z; m2 = (m2 > 0.f) ? m2 : NEG * m2;
        float m3 = gc.w + grd.w; m3 = (m3 > 0.f) ? m3 : NEG * m3;
        float p = at.x * m0 + at.y * m1 + at.z * m2 + at.w * m3;
        p += __shfl_xor_sync(0xffffffffu, p, 1);
        p += __shfl_xor_sync(0xffffffffu, p, 2);
        p += __shfl_xor_sync(0xffffffffu, p, 4);
        float w = (j <= deg) ? __expf(p) : 0.f;
        acc.x += w * gc.x;
        acc.y += w * gc.y;
        acc.z += w * gc.z;
        acc.w += w * gc.w;
        den += w;
    }

    if (dvalid) {
        const float inv = 1.f / den;
        const float4 b = reinterpret_cast<const float4*>(bias)[lg];
        reinterpret_cast<float4*>(out)[d * 8 + lg] =
            make_float4(acc.x * inv + b.x, acc.y * inv + b.y,
                        acc.z * inv + b.z, acc.w * inv + b.w);
    }
}

// ---------------- launch ----------------
extern "C" void kernel_launch(void* const* d_in, const int* in_sizes, int n_in,
                              void* d_out, int out_size) {
    const float* x    = (const float*)d_in[0];
    const int*   ei   = (const int*)d_in[1];
    const float* Wl1  = (const float*)d_in[2];
    const float* bl1  = (const float*)d_in[3];
    const float* Wr1  = (const float*)d_in[4];
    const float* br1  = (const float*)d_in[5];
    const float* att1 = (const float*)d_in[6];
    const float* bias1= (const float*)d_in[7];
    const float* Wl2  = (const float*)d_in[8];
    const float* bl2  = (const float*)d_in[9];
    const float* Wr2  = (const float*)d_in[10];
    const float* br2  = (const float*)d_in[11];
    const float* att2 = (const float*)d_in[12];
    const float* bias2= (const float*)d_in[13];
    float* out = (float*)d_out;

    // gemm1: M=128, CT=8, RB=64  -> smem (64*128 + 128*128)*4 = 98304
    // gemm2: M=32,  CT=4, RB=128 -> smem (128*128 + 128*32)*4 = 81920
    cudaFuncSetAttribute((gemm_kernel<128, 8, 64>),
                         cudaFuncAttributeMaxDynamicSharedMemorySize, 98304);
    cudaFuncSetAttribute((gemm_kernel<32, 4, 128>),
                         cudaFuncAttributeMaxDynamicSharedMemorySize, 81920);

    float *gl1p, *gr1p, *h1p, *gl2p, *gr2p;
    cudaGetSymbolAddress((void**)&gl1p, g_gl1);
    cudaGetSymbolAddress((void**)&gr1p, g_gr1);
    cudaGetSymbolAddress((void**)&h1p,  g_h1);
    cudaGetSymbolAddress((void**)&gl2p, g_gl2);
    cudaGetSymbolAddress((void**)&gr2p, g_gr2);

    // slots 1-3: CSR prefix; slot 4: gemm1 (profiled by ncu)
    csr_init_kernel<<<(NN + 255) / 256, 256>>>();
    csr_hist_kernel<<<(EE + 255) / 256, 256>>>(ei);
    csr_scan_kernel<<<1, 1024>>>();
    gemm_kernel<128, 8, 64><<<dim3((NN + 63) / 64, 2), 128, 98304>>>(
        x, NN, Wl1, bl1, gl1p, Wr1, br1, gr1p);
    csr_fill_kernel<<<(EE + 255) / 256, 256>>>(ei);

    agg1_kernel<<<(NN + 7) / 8, 256>>>(att1, bias1);

    gemm_kernel<32, 4, 128><<<dim3((NN + 127) / 128, 2), 128, 81920>>>(
        h1p, NN, Wl2, bl2, gl2p, Wr2, br2, gr2p);
    agg2_kernel<<<(NN + 31) / 32, 256>>>(att2, bias2, out);
}